// round 17
// baseline (speedup 1.0000x reference)
#include <cuda_runtime.h>
#include <cstdint>

#define HH 96
#define WW 96
#define HW 9216
#define CH 256
#define NB 2
#define NL 4
#define KK 2304   // CH*9

typedef unsigned long long ull;

// ---------------------------------------------------------------------------
// Scratch (static device globals: no allocation at runtime)
// ---------------------------------------------------------------------------
__device__ float g_bufA[NB * CH * HW];          // ping
__device__ float g_bufB[NB * CH * HW];          // pong
__device__ float g_off [NB * 18 * HW];          // offsets per layer
__device__ float g_WTm [KK * 256];              // transposed main weights  [c*9+k][oc]
__device__ float g_WTo [KK * 32];               // transposed offset weights [c*9+k][oc(pad32)]

// ---------------------------------------------------------------------------
// packed f32x2 helpers (FFMA2 — ptxas never emits these from C++)
// ---------------------------------------------------------------------------
__device__ __forceinline__ ull dupf(float v) {
    ull d; unsigned r = __float_as_uint(v);
    asm("mov.b64 %0, {%1, %1};" : "=l"(d) : "r"(r));
    return d;
}
__device__ __forceinline__ ull fma2(ull a, ull b, ull c) {
    ull d;
    asm("fma.rn.f32x2 %0, %1, %2, %3;" : "=l"(d) : "l"(a), "l"(b), "l"(c));
    return d;
}
__device__ __forceinline__ void unpack2(float& lo, float& hi, ull v) {
    unsigned a, b;
    asm("mov.b64 {%0, %1}, %2;" : "=r"(a), "=r"(b) : "l"(v));
    lo = __uint_as_float(a); hi = __uint_as_float(b);
}
// 16B shared load returning two packed f32x2 (pixel pairs, no repack needed)
__device__ __forceinline__ void lds_v2u64(ull& a, ull& b, const float* p) {
    unsigned sa = (unsigned)__cvta_generic_to_shared(p);
    asm volatile("ld.shared.v2.u64 {%0, %1}, [%2];" : "=l"(a), "=l"(b) : "r"(sa));
}

// ---------------------------------------------------------------------------
// Weight transpose: W[o][c*9+k]  ->  WT[c*9+k][o], zero-padded to OCP columns
// ---------------------------------------------------------------------------
__global__ void transpose_w_kernel(const float* __restrict__ win,
                                   float* __restrict__ wout,
                                   int O_in, int OCP)
{
    int t = blockIdx.x * blockDim.x + threadIdx.x;
    int total = KK * OCP;
    if (t >= total) return;
    int idx = t / OCP;
    int o   = t - idx * OCP;
    wout[t] = (o < O_in) ? win[o * KK + idx] : 0.0f;
}

// ---------------------------------------------------------------------------
// Unified deformable-conv GEMM, packed-f32x2 micro-GEMM.
//   Out[oc][pix] = sum_{c,k} WT[c*9+k][oc] * S[c][k][pix]  (+bias, optional relu)
// Block: OC_TILE oc x 128 px, 256 threads, thread tile MT oc x 8 px.
// Accumulators are f32x2 packed along the pixel axis.
// ---------------------------------------------------------------------------
template <int OC_TILE, int MT, bool HAS_OFF, bool RELU>
__global__ __launch_bounds__(256, 2)
void deform_gemm_kernel(const float* __restrict__ xin,
                        const float* __restrict__ off,
                        const float* __restrict__ WT, int OC_PAD,
                        const float* __restrict__ bias,
                        float* __restrict__ out, int OC_OUT)
{
    constexpr int PX = 128;
    constexpr int CC = 4;           // channels per K-chunk
    constexpr int THREADS = 256;
    constexpr int NPOS = 9 * PX;

    const int tid  = threadIdx.x;
    const int tx   = tid & 15;      // pixel group -> 8 px each
    const int ty   = tid >> 4;      // oc group    -> MT oc each
    const int b    = blockIdx.z;
    const int pix0 = blockIdx.x * PX;
    const int ocb  = blockIdx.y * OC_TILE;

    extern __shared__ unsigned char smraw[];
    // carve: [geom idx NPOS*16][geom wt NPOS*16][sS CC*9*PX*4][sW 36*OC_TILE*4]
    int*   sIdx = (int*)smraw;
    float* sWt  = (float*)(smraw + (HAS_OFF ? NPOS * 16 : 0));
    float* sS   = (float*)(smraw + (HAS_OFF ? NPOS * 32 : 0));
    float* sW   = sS + CC * 9 * PX;

    // ---- per-block sampling geometry (channel-independent) ----
    if (HAS_OFF) {
        for (int it = tid; it < NPOS; it += THREADS) {
            int k   = it / PX;
            int p   = it - k * PX;
            int pix = pix0 + p;
            int y   = pix / WW;
            int x   = pix - y * WW;
            float oy = __ldg(off + (b * 18 + 2 * k    ) * HW + pix);
            float ox = __ldg(off + (b * 18 + 2 * k + 1) * HW + pix);
            float py  = (float)(y - 1 + k / 3) + oy;
            float pxf = (float)(x - 1 + k % 3) + ox;
            float y0f = floorf(py), x0f = floorf(pxf);
            float fy = py - y0f, fx = pxf - x0f;
            int y0 = (int)y0f, x0 = (int)x0f;
            float wy[2] = {1.0f - fy, fy};
            float wx[2] = {1.0f - fx, fx};
            int4   idv;
            float4 wtv;
            int   idt[4];
            float wtt[4];
#pragma unroll
            for (int j = 0; j < 4; j++) {
                int yy = y0 + (j >> 1);
                int xx = x0 + (j & 1);
                bool v = (yy >= 0) && (yy < HH) && (xx >= 0) && (xx < WW);
                int yc = min(max(yy, 0), HH - 1);
                int xc = min(max(xx, 0), WW - 1);
                idt[j] = yc * WW + xc;
                wtt[j] = v ? (wy[j >> 1] * wx[j & 1]) : 0.0f;
            }
            idv.x = idt[0]; idv.y = idt[1]; idv.z = idt[2]; idv.w = idt[3];
            wtv.x = wtt[0]; wtv.y = wtt[1]; wtv.z = wtt[2]; wtv.w = wtt[3];
            reinterpret_cast<int4*  >(sIdx)[it] = idv;
            reinterpret_cast<float4*>(sWt )[it] = wtv;
        }
        __syncthreads();
    }

    ull acc[MT][4];
#pragma unroll
    for (int i = 0; i < MT; i++)
#pragma unroll
        for (int j = 0; j < 4; j++) acc[i][j] = 0ull;

    const float* xb = xin + (size_t)b * CH * HW;
    const float* sSbase = sS + tx * 8;
    const float* sWbase = sW + ty * MT;

    for (int c0 = 0; c0 < CH; c0 += CC) {
        __syncthreads();   // previous chunk's GEMM reads done before overwrite

        // ---- build sampled S for CC channels ----
        if (HAS_OFF) {
            for (int v = tid; v < CC * NPOS; v += THREADS) {
                int cc = v / NPOS;
                int it = v - cc * NPOS;
                const float* xc = xb + (c0 + cc) * HW;
                int4   id = reinterpret_cast<const int4*  >(sIdx)[it];
                float4 w  = reinterpret_cast<const float4*>(sWt )[it];
                float s = w.x * __ldg(xc + id.x) + w.y * __ldg(xc + id.y)
                        + w.z * __ldg(xc + id.z) + w.w * __ldg(xc + id.w);
                sS[v] = s;
            }
        } else {
            for (int v = tid; v < CC * NPOS; v += THREADS) {
                int cc = v / NPOS;
                int it = v - cc * NPOS;
                int k  = it / PX;
                int p  = it - k * PX;
                int pix = pix0 + p;
                int y = pix / WW;
                int x = pix - y * WW;
                int yy = y + k / 3 - 1;
                int xx = x + (k % 3) - 1;
                float s = 0.0f;
                if (yy >= 0 && yy < HH && xx >= 0 && xx < WW)
                    s = __ldg(xb + (c0 + cc) * HW + yy * WW + xx);
                sS[v] = s;
            }
        }

        // ---- stage transposed weights (coalesced float4) ----
        for (int v = tid; v < CC * 9 * OC_TILE / 4; v += THREADS) {
            int row  = v / (OC_TILE / 4);
            int col4 = v - row * (OC_TILE / 4);
            reinterpret_cast<float4*>(sW)[v] = *reinterpret_cast<const float4*>(
                WT + (size_t)(c0 * 9 + row) * OC_PAD + ocb + col4 * 4);
        }
        __syncthreads();

        // ---- FFMA2 micro-GEMM: MT oc x 8 px per thread ----
#pragma unroll
        for (int cc = 0; cc < CC; cc++) {
#pragma unroll
            for (int k = 0; k < 9; k++) {
                const int r = cc * 9 + k;
                ull s[4];
                lds_v2u64(s[0], s[1], sSbase + r * PX);
                lds_v2u64(s[2], s[3], sSbase + r * PX + 4);
                ull w[MT];
                if constexpr (MT == 8) {
                    float4 wa = *reinterpret_cast<const float4*>(sWbase + r * OC_TILE);
                    float4 wb = *reinterpret_cast<const float4*>(sWbase + r * OC_TILE + 4);
                    w[0] = dupf(wa.x); w[1] = dupf(wa.y); w[2] = dupf(wa.z); w[3] = dupf(wa.w);
                    w[4] = dupf(wb.x); w[5] = dupf(wb.y); w[6] = dupf(wb.z); w[7] = dupf(wb.w);
                } else {
                    float2 wa = *reinterpret_cast<const float2*>(sWbase + r * OC_TILE);
                    w[0] = dupf(wa.x); w[1] = dupf(wa.y);
                }
#pragma unroll
                for (int i = 0; i < MT; i++) {
#pragma unroll
                    for (int j = 0; j < 4; j++)
                        acc[i][j] = fma2(w[i], s[j], acc[i][j]);
                }
            }
        }
    }

    // ---- epilogue: unpack, bias (+relu), vectorized store ----
#pragma unroll
    for (int i = 0; i < MT; i++) {
        int oc = ocb + ty * MT + i;
        if (oc < OC_OUT) {
            float bv = __ldg(bias + oc);
            float4 o0, o1;
            unpack2(o0.x, o0.y, acc[i][0]);
            unpack2(o0.z, o0.w, acc[i][1]);
            unpack2(o1.x, o1.y, acc[i][2]);
            unpack2(o1.z, o1.w, acc[i][3]);
            o0.x += bv; o0.y += bv; o0.z += bv; o0.w += bv;
            o1.x += bv; o1.y += bv; o1.z += bv; o1.w += bv;
            if (RELU) {
                o0.x = fmaxf(o0.x, 0.0f); o0.y = fmaxf(o0.y, 0.0f);
                o0.z = fmaxf(o0.z, 0.0f); o0.w = fmaxf(o0.w, 0.0f);
                o1.x = fmaxf(o1.x, 0.0f); o1.y = fmaxf(o1.y, 0.0f);
                o1.z = fmaxf(o1.z, 0.0f); o1.w = fmaxf(o1.w, 0.0f);
            }
            float* dst = out + ((size_t)b * OC_OUT + oc) * HW + pix0 + tx * 8;
            *reinterpret_cast<float4*>(dst)     = o0;
            *reinterpret_cast<float4*>(dst + 4) = o1;
        }
    }
}

// ---------------------------------------------------------------------------
// Launch: 4 layers, each = transpose weights, offset conv, deformable conv.
// All launches on the default stream (serialized); graph-capturable.
// ---------------------------------------------------------------------------
extern "C" void kernel_launch(void* const* d_in, const int* in_sizes, int n_in,
                              void* d_out, int out_size)
{
    (void)in_sizes; (void)n_in; (void)out_size;
    const float* x     = (const float*)d_in[0];
    const float* off_w = (const float*)d_in[1];
    const float* off_b = (const float*)d_in[2];
    const float* dw    = (const float*)d_in[3];
    const float* db    = (const float*)d_in[4];
    float* out = (float*)d_out;

    float *pA, *pB, *pOff, *pWTm, *pWTo;
    cudaGetSymbolAddress((void**)&pA,   g_bufA);
    cudaGetSymbolAddress((void**)&pB,   g_bufB);
    cudaGetSymbolAddress((void**)&pOff, g_off);
    cudaGetSymbolAddress((void**)&pWTm, g_WTm);
    cudaGetSymbolAddress((void**)&pWTo, g_WTo);

    // dynamic smem: geom(36864) + sS(18432) + sW(18432) for main; sS+sW for offset
    constexpr int SMEM_MAIN = 9 * 128 * 32 + 4 * 9 * 128 * 4 + 36 * 128 * 4;   // 73728
    constexpr int SMEM_OFF  = 4 * 9 * 128 * 4 + 36 * 32 * 4;                   // 23040

    cudaFuncSetAttribute((const void*)deform_gemm_kernel<128, 8, true, true>,
                         cudaFuncAttributeMaxDynamicSharedMemorySize, SMEM_MAIN);
    cudaFuncSetAttribute((const void*)deform_gemm_kernel<32, 2, false, false>,
                         cudaFuncAttributeMaxDynamicSharedMemorySize, SMEM_OFF);

    for (int i = 0; i < NL; i++) {
        // transpose this layer's weights into [c*9+k][oc] layout
        transpose_w_kernel<<<(KK * 32  + 255) / 256, 256>>>(off_w + (size_t)i * 18 * KK, pWTo, 18, 32);
        transpose_w_kernel<<<(KK * 256 + 255) / 256, 256>>>(dw    + (size_t)i * CH * KK, pWTm, 256, 256);

        const float* in_i = (i == 0) ? x : ((i & 1) ? pA : pB);
        float* out_i = (i == 3) ? out : ((i & 1) ? pB : pA);

        // offset conv: 256->18 (padded to 32), zero offsets path, no relu
        dim3 g1(HW / 128, 1, NB);
        deform_gemm_kernel<32, 2, false, false><<<g1, 256, SMEM_OFF>>>(
            in_i, nullptr, pWTo, 32, off_b + (size_t)i * 18, pOff, 18);

        // deformable conv: 256->256, bilinear path, bias + relu
        dim3 g2(HW / 128, 2, NB);
        deform_gemm_kernel<128, 8, true, true><<<g2, 256, SMEM_MAIN>>>(
            in_i, pOff, pWTm, 256, db + (size_t)i * CH, out_i, 256);
    }
}